// round 4
// baseline (speedup 1.0000x reference)
#include <cuda_runtime.h>
#include <cstdint>

// ROI Align, P=7, S=2, SCALE=0.125
// x: (8, 256, 100, 100) fp32   rois: (512, 5) fp32   out: (512, 256, 7, 7) fp32
//
// Geometry kernel folds, per (roi, bin-row) and (roi, bin-col):
//   y: 4 consecutive rows starting at yb (16B-irrelevant) with 4 weights
//      (both y-samples + edge clamps + 0.25 scale folded in)
//   x: 8 consecutive floats starting at 16B-aligned wb with 8 weights
//      (both x-samples + edge clamps folded in)
// Main kernel: per output, 8 x LDG.128 (4 rows x 2 float4) + 36 FMA.

#define C_   256
#define H_   100
#define W_   100
#define HW_  10000
#define R_   512
#define TOTAL (R_ * C_ * 49)

__device__ float4 g_yw[R_][7];    // 4 row weights (pre-scaled by 0.25)
__device__ int    g_yo[R_][7];    // b*C*HW + yb*W
__device__ float4 g_xw[R_][14];   // 8 window weights as 2 float4 per pw
__device__ int    g_xo[R_][7];    // wb (aligned window base, floats)

__device__ __forceinline__ void axis_terms(float c, int L,
                                           int& lo, int& hi,
                                           float& wlo, float& whi) {
    bool valid = (c > -1.0f) && (c < (float)L);
    float cc = fminf(fmaxf(c, 0.0f), (float)(L - 1));
    int l = (int)floorf(cc);
    if (l > L - 1) l = L - 1;
    int h = min(l + 1, L - 1);
    float frac = cc - (float)l;
    lo = l; hi = h;
    wlo = valid ? (1.0f - frac) : 0.0f;
    whi = valid ? frac : 0.0f;
}

__global__ void geom_kernel(const float* __restrict__ rois) {
    int t = blockIdx.x * blockDim.x + threadIdx.x;
    if (t >= R_ * 14) return;
    int r = t / 14;
    int s = t - r * 14;

    const float* roi = rois + (size_t)r * 5;
    float r0 = __ldg(roi + 0);
    float r1 = __ldg(roi + 1);
    float r2 = __ldg(roi + 2);
    float r3 = __ldg(roi + 3);
    float r4 = __ldg(roi + 4);

    int b = (int)r0;
    float sx = r1 * 0.125f - 0.5f;
    float sy = r2 * 0.125f - 0.5f;
    float bw = (r3 * 0.125f - 0.5f - sx) * (1.0f / 7.0f);
    float bh = (r4 * 0.125f - 0.5f - sy) * (1.0f / 7.0f);

    if (s < 7) {
        int ph = s;
        float y0 = fmaf((float)ph + 0.25f, bh, sy);
        float y1 = fmaf((float)ph + 0.75f, bh, sy);
        int l0, h0, l1, h1; float w00, w01, w10, w11;
        axis_terms(y0, H_, l0, h0, w00, w01);
        axis_terms(y1, H_, l1, h1, w10, w11);
        int yb = min(l0, H_ - 4);
        float wv[4] = {0.f, 0.f, 0.f, 0.f};
        wv[l0 - yb] += w00;
        wv[h0 - yb] += w01;
        wv[l1 - yb] += w10;
        wv[h1 - yb] += w11;
        g_yw[r][ph] = make_float4(wv[0] * 0.25f, wv[1] * 0.25f,
                                  wv[2] * 0.25f, wv[3] * 0.25f);
        g_yo[r][ph] = b * C_ * HW_ + yb * W_;
    } else {
        int pw = s - 7;
        float x0 = fmaf((float)pw + 0.25f, bw, sx);
        float x1 = fmaf((float)pw + 0.75f, bw, sx);
        int l0, h0, l1, h1; float w00, w01, w10, w11;
        axis_terms(x0, W_, l0, h0, w00, w01);
        axis_terms(x1, W_, l1, h1, w10, w11);
        int wb = min(l0 & ~3, W_ - 8);
        float wv[8] = {0.f, 0.f, 0.f, 0.f, 0.f, 0.f, 0.f, 0.f};
        wv[l0 - wb] += w00;
        wv[h0 - wb] += w01;
        wv[l1 - wb] += w10;
        wv[h1 - wb] += w11;
        g_xw[r][2 * pw]     = make_float4(wv[0], wv[1], wv[2], wv[3]);
        g_xw[r][2 * pw + 1] = make_float4(wv[4], wv[5], wv[6], wv[7]);
        g_xo[r][pw] = wb;
    }
}

__global__ void __launch_bounds__(256)
roi_main(const float* __restrict__ x, float* __restrict__ out) {
    __shared__ float4 syw[7];
    __shared__ float4 sxw[14];
    __shared__ int    syo[7];
    __shared__ int    sxo[7];

    int r = blockIdx.x / 49;          // block never crosses a roi (12544/256=49)
    int tid = threadIdx.x;
    if (tid < 7)                 syw[tid] = g_yw[r][tid];
    else if (tid >= 32 && tid < 46) sxw[tid - 32] = g_xw[r][tid - 32];
    else if (tid >= 64 && tid < 71) syo[tid - 64] = g_yo[r][tid - 64];
    else if (tid >= 96 && tid < 103) sxo[tid - 96] = g_xo[r][tid - 96];
    __syncthreads();

    int o   = blockIdx.x * 256 + tid;
    int bin = o % 49;
    int c   = (o / 49) & (C_ - 1);
    int ph  = bin / 7;
    int pw  = bin - ph * 7;

    float4 wy  = syw[ph];
    float4 wa  = sxw[2 * pw];
    float4 wb4 = sxw[2 * pw + 1];
    const float* p = x + syo[ph] + c * HW_ + sxo[pw];

    float acc = 0.0f;
#pragma unroll
    for (int k = 0; k < 4; k++) {
        float4 u = __ldg((const float4*)(p + k * W_));
        float4 v = __ldg((const float4*)(p + k * W_ + 4));
        float h = u.x * wa.x + u.y * wa.y + u.z * wa.z + u.w * wa.w
                + v.x * wb4.x + v.y * wb4.y + v.z * wb4.z + v.w * wb4.w;
        float wk = (k == 0) ? wy.x : (k == 1) ? wy.y : (k == 2) ? wy.z : wy.w;
        acc = fmaf(wk, h, acc);
    }

    out[o] = acc;
}

extern "C" void kernel_launch(void* const* d_in, const int* in_sizes, int n_in,
                              void* d_out, int out_size) {
    const float* x    = (const float*)d_in[0];
    const float* rois = (const float*)d_in[1];
    float* out = (float*)d_out;

    geom_kernel<<<(R_ * 14 + 255) / 256, 256>>>(rois);
    roi_main<<<TOTAL / 256, 256>>>(x, out);
}

// round 5
// speedup vs baseline: 1.2507x; 1.2507x over previous
#include <cuda_runtime.h>
#include <cstdint>

// ROI Align, P=7, S=2, SCALE=0.125
// x: (8, 256, 100, 100) fp32   rois: (512, 5) fp32   out: (512, 256, 7, 7) fp32
//
// geom_kernel: per (roi, axis-sample) bilinear terms -> 448B/roi table.
// roi_mc:      one thread = one bin x 4 consecutive channels. Geometry read
//              as 4x LDG.128 (warp-dedup'd), 16 tap offsets computed once,
//              reused across channels via LDG immediate offsets (k*HW).

#define C_   256
#define H_   100
#define W_   100
#define HW_  10000
#define R_   512
#define MC   4
#define CG_  (C_ / MC)                 // 64 channel groups
#define TPR  (CG_ * 49)                // 3136 threads per roi
#define NTHREADS 256

__device__ int4 g_geom[R_][28];  // [0..13]  y: {loW, hiW, wy0*0.25, wy1*0.25}
                                 // [14..27] x: {xb, wx0, wx1, roiBase}

__device__ __forceinline__ void axis_terms(float c, int L,
                                           int& lo, int& hi,
                                           float& wlo, float& whi) {
    bool valid = (c > -1.0f) && (c < (float)L);
    float cc = fminf(fmaxf(c, 0.0f), (float)(L - 1));
    int l = (int)floorf(cc);
    if (l > L - 1) l = L - 1;
    int h = min(l + 1, L - 1);
    float frac = cc - (float)l;
    lo = l; hi = h;
    wlo = valid ? (1.0f - frac) : 0.0f;
    whi = valid ? frac : 0.0f;
}

__global__ void geom_kernel(const float* __restrict__ rois) {
    int t = blockIdx.x * blockDim.x + threadIdx.x;
    if (t >= R_ * 28) return;
    int r = t / 28;
    int s = t - r * 28;

    const float* roi = rois + (size_t)r * 5;
    float r0 = __ldg(roi + 0);
    float r1 = __ldg(roi + 1);
    float r2 = __ldg(roi + 2);
    float r3 = __ldg(roi + 3);
    float r4 = __ldg(roi + 4);

    int b = (int)r0;
    float sx = r1 * 0.125f - 0.5f;
    float sy = r2 * 0.125f - 0.5f;
    float bw = (r3 * 0.125f - 0.5f - sx) * (1.0f / 7.0f);
    float bh = (r4 * 0.125f - 0.5f - sy) * (1.0f / 7.0f);

    int4 e;
    if (s < 14) {
        float pos = fmaf((float)(s >> 1) + ((s & 1) ? 0.75f : 0.25f), bh, sy);
        int lo, hi; float w0, w1;
        axis_terms(pos, H_, lo, hi, w0, w1);
        e = make_int4(lo * W_, hi * W_,
                      __float_as_int(w0 * 0.25f), __float_as_int(w1 * 0.25f));
    } else {
        int s2 = s - 14;
        float pos = fmaf((float)(s2 >> 1) + ((s2 & 1) ? 0.75f : 0.25f), bw, sx);
        int lo, hi; float w0, w1;
        axis_terms(pos, W_, lo, hi, w0, w1);
        // Fold hi==lo (right edge) into weights so consumer reads {xb, xb+1}.
        int xb; float v0, v1;
        if (lo == W_ - 1) { xb = W_ - 2; v0 = 0.0f; v1 = w0 + w1; }
        else              { xb = lo;     v0 = w0;   v1 = w1; }
        e = make_int4(xb, __float_as_int(v0), __float_as_int(v1), b * C_ * HW_);
    }
    g_geom[r][s] = e;
}

__global__ void __launch_bounds__(NTHREADS)
roi_mc(const float* __restrict__ x, float* __restrict__ out) {
    int t   = blockIdx.x * NTHREADS + threadIdx.x;   // 512*3136 threads exactly
    int r   = t / TPR;
    int l   = t - r * TPR;
    int cg  = l / 49;
    int bin = l - cg * 49;
    int ph  = bin / 7;
    int pw  = bin - ph * 7;

    const int4* G = &g_geom[r][0];
    int4 gy0 = __ldg(G + 2 * ph);
    int4 gy1 = __ldg(G + 2 * ph + 1);
    int4 gx0 = __ldg(G + 14 + 2 * pw);
    int4 gx1 = __ldg(G + 14 + 2 * pw + 1);

    const float* p = x + gx0.w + cg * (MC * HW_);

    const int xa = gx0.x, xb = gx1.x;
    const int a0 = gy0.x + xa, a1 = gy0.y + xa;   // sample-0 rows
    const int b0 = gy1.x + xa, b1 = gy1.y + xa;   // sample-1 rows
    const int dx = xb - xa;

    const float wx00 = __int_as_float(gx0.y), wx01 = __int_as_float(gx0.z);
    const float wx10 = __int_as_float(gx1.y), wx11 = __int_as_float(gx1.z);
    const float wyA0 = __int_as_float(gy0.z), wyA1 = __int_as_float(gy0.w);
    const float wyB0 = __int_as_float(gy1.z), wyB1 = __int_as_float(gy1.w);

    float res[MC];
#pragma unroll
    for (int k = 0; k < MC; k++) {
        const float* pk = p + k * HW_;
        float hA0 = wx00 * __ldg(pk + a0)      + wx01 * __ldg(pk + a0 + 1)
                  + wx10 * __ldg(pk + a0 + dx) + wx11 * __ldg(pk + a0 + dx + 1);
        float hA1 = wx00 * __ldg(pk + a1)      + wx01 * __ldg(pk + a1 + 1)
                  + wx10 * __ldg(pk + a1 + dx) + wx11 * __ldg(pk + a1 + dx + 1);
        float hB0 = wx00 * __ldg(pk + b0)      + wx01 * __ldg(pk + b0 + 1)
                  + wx10 * __ldg(pk + b0 + dx) + wx11 * __ldg(pk + b0 + dx + 1);
        float hB1 = wx00 * __ldg(pk + b1)      + wx01 * __ldg(pk + b1 + 1)
                  + wx10 * __ldg(pk + b1 + dx) + wx11 * __ldg(pk + b1 + dx + 1);
        res[k] = wyA0 * hA0 + wyA1 * hA1 + wyB0 * hB0 + wyB1 * hB1;
    }

    float* po = out + ((size_t)r * C_ + cg * MC) * 49 + bin;
#pragma unroll
    for (int k = 0; k < MC; k++)
        po[k * 49] = res[k];
}

extern "C" void kernel_launch(void* const* d_in, const int* in_sizes, int n_in,
                              void* d_out, int out_size) {
    const float* x    = (const float*)d_in[0];
    const float* rois = (const float*)d_in[1];
    float* out = (float*)d_out;

    geom_kernel<<<(R_ * 28 + 255) / 256, 256>>>(rois);
    roi_mc<<<(R_ * TPR) / NTHREADS, NTHREADS>>>(x, out);
}